// round 7
// baseline (speedup 1.0000x reference)
#include <cuda_runtime.h>

#define BB 32
#define CC 256
#define LL 64
#define NHKD 16
#define QKV_CH 48

// scratch (device globals; no allocations)
__device__ __align__(16) float g_xh[BB*CC*LL];        // mean over W : [b][c][h]
__device__ __align__(16) float g_xw[BB*CC*LL];        // mean over H : [b][c][w]
__device__ __align__(16) float g_qkv[BB*2*QKV_CH*LL]; // [(b*2+axis)][o][l]
__device__ __align__(16) float g_att[BB*2*NHKD*LL];   // axial attention outputs
__device__ __align__(16) float g_P[BB*CC*LL];         // (A*fs+fsh)*g*0.1
__device__ __align__(16) float g_Q[BB*CC*LL];         // (B*fs)*g*0.1

// ---------------------------------------------------------------------------
// K1: per-(b,c) 64x64 tile -> row means (over W) and col means (over H)
// ---------------------------------------------------------------------------
__global__ void k1_reduce(const float* __restrict__ x) {
    int bc = blockIdx.x;                       // b*256 + c
    const float4* xt = (const float4*)(x + (size_t)bc * 4096);
    int t = threadIdx.x;                       // 256 threads
    __shared__ float scol[64];
    if (t < 64) scol[t] = 0.f;
    __syncthreads();

    float c0 = 0.f, c1 = 0.f, c2 = 0.f, c3 = 0.f;
    #pragma unroll
    for (int i = 0; i < 4; ++i) {
        int j = t + 256 * i;                   // float4 index in [0,1024)
        float4 v = xt[j];
        float rs = v.x + v.y + v.z + v.w;
        #pragma unroll
        for (int off = 8; off >= 1; off >>= 1)
            rs += __shfl_xor_sync(0xffffffffu, rs, off);
        if ((t & 15) == 0)
            g_xh[bc * 64 + (j >> 4)] = rs * (1.f / 64.f);
        c0 += v.x; c1 += v.y; c2 += v.z; c3 += v.w;
    }
    c0 += __shfl_xor_sync(0xffffffffu, c0, 16);
    c1 += __shfl_xor_sync(0xffffffffu, c1, 16);
    c2 += __shfl_xor_sync(0xffffffffu, c2, 16);
    c3 += __shfl_xor_sync(0xffffffffu, c3, 16);
    if ((t & 31) < 16) {
        int cb = (t & 15) * 4;
        atomicAdd(&scol[cb + 0], c0);
        atomicAdd(&scol[cb + 1], c1);
        atomicAdd(&scol[cb + 2], c2);
        atomicAdd(&scol[cb + 3], c3);
    }
    __syncthreads();
    if (t < 64) g_xw[bc * 64 + t] = scol[t] * (1.f / 64.f);
}

// ---------------------------------------------------------------------------
// K2: qkv projection. 128 blocks (b,axis,l-half), 384 threads.
// 12 o-groups x 4 outputs; weights staged transposed so the inner loop is
// 1 LDS (sx) + 1 warp-uniform LDS.128 (weights) + 4 FFMA.
// Per-thread FMA = 4*256 = 1024 -> short critical path.
// ---------------------------------------------------------------------------
__global__ void k2_qkv(const float* __restrict__ w_qkv,
                       const float* __restrict__ qs,
                       const float* __restrict__ qsh,
                       const float* __restrict__ pos_h,
                       const float* __restrict__ pos_w) {
    int blk   = blockIdx.x;        // 0..127
    int half  = blk & 1;
    int baxis = blk >> 1;          // b*2+axis in [0,64)
    int axis  = baxis & 1;
    int b     = baxis >> 1;
    const float* xm = (axis == 0 ? g_xh : g_xw) + b * CC * 64;

    __shared__ __align__(16) float swT[64][QKV_CH];  // 12 KB [cl][o]
    __shared__ float sx[64][32];                     // 8 KB  [c_local][l_local]

    int t    = threadIdx.x;        // 0..383
    int lloc = t & 31;
    int og   = t >> 5;             // 12 o-groups of 4 (warp-uniform)

    float acc0 = 0.f, acc1 = 0.f, acc2 = 0.f, acc3 = 0.f;
    for (int cc = 0; cc < 256; cc += 64) {
        for (int e = t; e < QKV_CH * 64; e += 384) {
            int o = e >> 6, cl = e & 63;
            swT[cl][o] = w_qkv[o * 256 + cc + cl];
        }
        for (int e = t; e < 64 * 32; e += 384) {
            int cl = e >> 5, ll = e & 31;
            sx[cl][ll] = xm[(cc + cl) * 64 + half * 32 + ll];
        }
        __syncthreads();
        const float4* swT4 = (const float4*)swT;   // 12 float4 per row
        #pragma unroll 8
        for (int cl = 0; cl < 64; ++cl) {
            float  xv = sx[cl][lloc];
            float4 w  = swT4[cl * 12 + og];        // warp-uniform broadcast
            acc0 += w.x * xv; acc1 += w.y * xv;
            acc2 += w.z * xv; acc3 += w.w * xv;
        }
        __syncthreads();
    }

    int l = half * 32 + lloc;
    const float* pos = axis ? pos_w : pos_h;
    float accv[4] = {acc0, acc1, acc2, acc3};
    #pragma unroll
    for (int j = 0; j < 4; ++j) {
        int o = og * 4 + j;
        float v = accv[j] * qs[o] + qsh[o];
        if (o < 32) v += pos[(o & 15) * 64 + l];   // pos added to q and k
        g_qkv[baxis * QKV_CH * 64 + o * 64 + l] = v;
    }
}

// ---------------------------------------------------------------------------
// K3: axial attention. 64 blocks (b,axis), 128 threads (i = t&63, head = t>>6)
// ---------------------------------------------------------------------------
__global__ void k3_attn() {
    int blk = blockIdx.x;                  // b*2+axis in [0,64)
    __shared__ float sT[64][52];           // [l][channel], padded
    int t = threadIdx.x;
    for (int e = t; e < QKV_CH * 64; e += 128) {
        int o = e >> 6, l = e & 63;
        sT[l][o] = g_qkv[blk * QKV_CH * 64 + e];
    }
    __syncthreads();

    int i  = t & 63;
    int qo = (t >> 6) * 8;

    float qreg[8];
    #pragma unroll
    for (int d = 0; d < 8; ++d) qreg[d] = sT[i][qo + d];

    float a[64];
    float m = -1e30f;
    #pragma unroll
    for (int j = 0; j < 64; ++j) {
        float s = 0.f;
        #pragma unroll
        for (int d = 0; d < 8; ++d) s += qreg[d] * sT[j][16 + qo + d];
        s *= 0.35355339059327373f;  // 8^-0.5
        a[j] = s;
        m = fmaxf(m, s);
    }
    float ssum = 0.f;
    #pragma unroll
    for (int j = 0; j < 64; ++j) {
        float e = __expf(a[j] - m);
        a[j] = e;
        ssum += e;
    }
    float inv = 1.f / ssum;

    float acc[8] = {0.f, 0.f, 0.f, 0.f, 0.f, 0.f, 0.f, 0.f};
    #pragma unroll
    for (int j = 0; j < 64; ++j) {
        float aj = a[j];
        #pragma unroll
        for (int d = 0; d < 8; ++d) acc[d] += aj * sT[j][32 + qo + d];
    }
    #pragma unroll
    for (int d = 0; d < 8; ++d)
        g_att[blk * NHKD * 64 + (qo + d) * 64 + i] = acc[d] * inv;
}

// ---------------------------------------------------------------------------
// K45: fused SE gate + P/Q production. 32 blocks (b), 256 threads.
// ---------------------------------------------------------------------------
__global__ void k45_gate_pq(const float* __restrict__ w_fusion,
                            const float* __restrict__ fs,
                            const float* __restrict__ fsh,
                            const float* __restrict__ wg1,
                            const float* __restrict__ g1s,
                            const float* __restrict__ g1sh,
                            const float* __restrict__ wg2,
                            const float* __restrict__ g2s,
                            const float* __restrict__ g2sh) {
    int b = blockIdx.x;
    int t = threadIdx.x;
    int lane = t & 31, wrp = t >> 5;       // 8 warps

    __shared__ float satt[2 * NHKD * 64];  // 8 KB: both axes' attention out
    __shared__ float meanf[32];
    __shared__ float y[256];
    __shared__ float t1[64];

    {
        const float4* src = (const float4*)(g_att + b * 2 * NHKD * 64);
        float4* dst = (float4*)satt;
        dst[t]       = src[t];
        dst[t + 256] = src[t + 256];
    }
    __syncthreads();

    // stage 1: channel means of fused input
    {
        int ch = t >> 3, sub = t & 7;
        const float* p = satt + ch * 64;
        float s = 0.f;
        #pragma unroll
        for (int i = 0; i < 8; ++i) s += p[sub + 8 * i];
        #pragma unroll
        for (int off = 4; off >= 1; off >>= 1)
            s += __shfl_xor_sync(0xffffffffu, s, off);
        if (sub == 0) meanf[ch] = s * (1.f / 64.f);
    }
    __syncthreads();

    // stage 2: y = cbn(w_fusion @ meanf)
    {
        const float4* wr = (const float4*)(w_fusion + t * 32);
        float s = 0.f;
        #pragma unroll
        for (int c4 = 0; c4 < 8; ++c4) {
            float4 wv = wr[c4];
            s += wv.x * meanf[c4 * 4 + 0] + wv.y * meanf[c4 * 4 + 1]
               + wv.z * meanf[c4 * 4 + 2] + wv.w * meanf[c4 * 4 + 3];
        }
        y[t] = s * fs[t] + fsh[t];
    }
    __syncthreads();

    // stage 3: t1 = silu(cbn(wg1 @ y)) — warp-per-row, coalesced lanes
    #pragma unroll
    for (int o = wrp; o < 64; o += 8) {
        const float* r = wg1 + o * 256;
        float s = 0.f;
        #pragma unroll
        for (int i = 0; i < 8; ++i) {
            int c = lane + 32 * i;
            s += r[c] * y[c];
        }
        #pragma unroll
        for (int off = 16; off >= 1; off >>= 1)
            s += __shfl_xor_sync(0xffffffffu, s, off);
        if (lane == 0) {
            s = s * g1s[o] + g1sh[o];
            t1[o] = s / (1.f + __expf(-s));
        }
    }
    __syncthreads();

    // stage 4: gate = sigmoid(cbn(wg2 @ t1))
    float gate;
    {
        const float4* wr = (const float4*)(wg2 + t * 64);
        float s = 0.f;
        #pragma unroll
        for (int c4 = 0; c4 < 16; ++c4) {
            float4 wv = wr[c4];
            s += wv.x * t1[c4 * 4 + 0] + wv.y * t1[c4 * 4 + 1]
               + wv.z * t1[c4 * 4 + 2] + wv.w * t1[c4 * 4 + 3];
        }
        s = s * g2s[t] + g2sh[t];
        gate = 1.f / (1.f + __expf(-s));
    }

    // stage 5: P and Q rows for o = t
    int o = t;
    float scale = fs[o] * gate * 0.1f;
    float biasP = fsh[o] * gate * 0.1f;
    const float4* sa4 = (const float4*)satt;

    #pragma unroll
    for (int axis = 0; axis < 2; ++axis) {
        float w[16];
        #pragma unroll
        for (int c = 0; c < 16; ++c) w[c] = w_fusion[o * 32 + axis * 16 + c];
        float bias = axis ? 0.f : biasP;
        float* dst = (axis ? g_Q : g_P) + (b * 256 + o) * 64;
        const float4* base = sa4 + axis * 256;

        #pragma unroll
        for (int lg = 0; lg < 16; ++lg) {
            float4 acc = {0.f, 0.f, 0.f, 0.f};
            #pragma unroll
            for (int c = 0; c < 16; ++c) {
                float4 xv = base[c * 16 + lg];
                acc.x += w[c] * xv.x; acc.y += w[c] * xv.y;
                acc.z += w[c] * xv.z; acc.w += w[c] * xv.w;
            }
            float4 r;
            r.x = acc.x * scale + bias; r.y = acc.y * scale + bias;
            r.z = acc.z * scale + bias; r.w = acc.w * scale + bias;
            ((float4*)dst)[lg] = r;
        }
    }
}

// ---------------------------------------------------------------------------
// K6: out[b,o,h,w] = x + P[b,o,h] + Q[b,o,w].  8192 blocks (b,o), 256 threads.
// (no cache hints — they measurably hurt in R6)
// ---------------------------------------------------------------------------
__global__ void k6_final(const float* __restrict__ x, float* __restrict__ out) {
    int blk = blockIdx.x;              // b*256+o
    __shared__ float  sp[64];
    __shared__ float4 sq4[16];
    int t = threadIdx.x;
    if (t < 64) sp[t] = g_P[blk * 64 + t];
    else if (t < 80) sq4[t - 64] = ((const float4*)(g_Q + blk * 64))[t - 64];
    __syncthreads();

    const float4* xi = (const float4*)(x + (size_t)blk * 4096);
    float4*       xo = (float4*)(out + (size_t)blk * 4096);
    #pragma unroll
    for (int i = 0; i < 4; ++i) {
        int j = t + 256 * i;
        float  p  = sp[j >> 4];
        float4 qv = sq4[j & 15];
        float4 xv = xi[j];
        float4 r;
        r.x = xv.x + p + qv.x;
        r.y = xv.y + p + qv.y;
        r.z = xv.z + p + qv.z;
        r.w = xv.w + p + qv.w;
        xo[j] = r;
    }
}

// ---------------------------------------------------------------------------
// Input identification by element count (robust to metadata ordering).
// ---------------------------------------------------------------------------
extern "C" void kernel_launch(void* const* d_in, const int* in_sizes, int n_in,
                              void* d_out, int out_size) {
    const float *x = 0, *w_qkv = 0, *qkv_scale = 0, *qkv_shift = 0;
    const float *pos_h = 0, *pos_w = 0, *w_fusion = 0;
    const float *fusion_scale = 0, *fusion_shift = 0;
    const float *w_g1 = 0, *g1_scale = 0, *g1_shift = 0;
    const float *w_g2 = 0, *g2_scale = 0, *g2_shift = 0;

    int n48 = 0, n64 = 0, n256 = 0, n1024 = 0, n16384 = 0;
    for (int i = 0; i < n_in; ++i) {
        const float* p = (const float*)d_in[i];
        switch (in_sizes[i]) {
            case 33554432: x = p; break;
            case 12288:    w_qkv = p; break;
            case 8192:     w_fusion = p; break;
            case 48:
                if (n48++ == 0) qkv_scale = p; else qkv_shift = p; break;
            case 1024:
                if (n1024++ == 0) pos_h = p; else pos_w = p; break;
            case 16384:
                if (n16384++ == 0) w_g1 = p; else w_g2 = p; break;
            case 64:
                if (n64++ == 0) g1_scale = p; else g1_shift = p; break;
            case 256:
                switch (n256++) {
                    case 0: fusion_scale = p; break;
                    case 1: fusion_shift = p; break;
                    case 2: g2_scale = p; break;
                    default: g2_shift = p; break;
                }
                break;
            default: break;
        }
    }
    float* out = (float*)d_out;

    k1_reduce<<<BB * CC, 256>>>(x);
    k2_qkv<<<128, 384>>>(w_qkv, qkv_scale, qkv_shift, pos_h, pos_w);
    k3_attn<<<64, 128>>>();
    k45_gate_pq<<<32, 256>>>(w_fusion, fusion_scale, fusion_shift,
                             w_g1, g1_scale, g1_shift,
                             w_g2, g2_scale, g2_shift);
    k6_final<<<BB * CC, 256>>>(x, out);
}

// round 8
// speedup vs baseline: 1.0954x; 1.0954x over previous
#include <cuda_runtime.h>

#define BB 32
#define CC 256
#define LL 64
#define NHKD 16
#define QKV_CH 48

// scratch (device globals; no allocations)
__device__ __align__(16) float g_xh[BB*CC*LL];        // mean over W : [b][c][h]
__device__ __align__(16) float g_xw[BB*CC*LL];        // mean over H : [b][c][w]
__device__ __align__(16) float g_att[BB*2*NHKD*LL];   // axial attention outputs
__device__ __align__(16) float g_mean[BB*2*NHKD];     // per-(b,axis) channel means
__device__ __align__(16) float g_P[BB*CC*LL];         // (A*fs+fsh)*g*0.1
__device__ __align__(16) float g_Q[BB*CC*LL];         // (B*fs)*g*0.1

// ---------------------------------------------------------------------------
// K1: per-(b,c) 64x64 tile -> row means (over W) and col means (over H)
// ---------------------------------------------------------------------------
__global__ void k1_reduce(const float* __restrict__ x) {
    int bc = blockIdx.x;                       // b*256 + c
    const float4* xt = (const float4*)(x + (size_t)bc * 4096);
    int t = threadIdx.x;                       // 256 threads
    __shared__ float scol[64];
    if (t < 64) scol[t] = 0.f;
    __syncthreads();

    float c0 = 0.f, c1 = 0.f, c2 = 0.f, c3 = 0.f;
    #pragma unroll
    for (int i = 0; i < 4; ++i) {
        int j = t + 256 * i;                   // float4 index in [0,1024)
        float4 v = xt[j];
        float rs = v.x + v.y + v.z + v.w;
        #pragma unroll
        for (int off = 8; off >= 1; off >>= 1)
            rs += __shfl_xor_sync(0xffffffffu, rs, off);
        if ((t & 15) == 0)
            g_xh[bc * 64 + (j >> 4)] = rs * (1.f / 64.f);
        c0 += v.x; c1 += v.y; c2 += v.z; c3 += v.w;
    }
    c0 += __shfl_xor_sync(0xffffffffu, c0, 16);
    c1 += __shfl_xor_sync(0xffffffffu, c1, 16);
    c2 += __shfl_xor_sync(0xffffffffu, c2, 16);
    c3 += __shfl_xor_sync(0xffffffffu, c3, 16);
    if ((t & 31) < 16) {
        int cb = (t & 15) * 4;
        atomicAdd(&scol[cb + 0], c0);
        atomicAdd(&scol[cb + 1], c1);
        atomicAdd(&scol[cb + 2], c2);
        atomicAdd(&scol[cb + 3], c3);
    }
    __syncthreads();
    if (t < 64) g_xw[bc * 64 + t] = scol[t] * (1.f / 64.f);
}

// ---------------------------------------------------------------------------
// K23: fused qkv projection + axial attention + channel means.
// 64 blocks (b*2+axis), 256 threads. Weights staged transposed (R6 win).
// ---------------------------------------------------------------------------
__global__ void k23_qkv_attn(const float* __restrict__ w_qkv,
                             const float* __restrict__ qs,
                             const float* __restrict__ qsh,
                             const float* __restrict__ pos_h,
                             const float* __restrict__ pos_w) {
    int blk  = blockIdx.x;         // b*2+axis in [0,64)
    int axis = blk & 1;
    int b    = blk >> 1;
    const float* xm = (axis == 0 ? g_xh : g_xw) + b * CC * 64;

    __shared__ __align__(16) float swT[64][QKV_CH];  // 12 KB [cl][o]
    __shared__ float sx[64][64];                     // 16 KB [c_local][l]
    __shared__ float sT[64][53];                     // 13.3 KB qkv^T [l][o]
    __shared__ float sM[NHKD][64];                   // 4 KB attention out

    int t  = threadIdx.x;
    int l  = t & 63;
    int og = t >> 6;                   // 4 o-groups of 12

    float acc[12];
    #pragma unroll
    for (int j = 0; j < 12; ++j) acc[j] = 0.f;

    for (int cc = 0; cc < 256; cc += 64) {
        for (int e = t; e < QKV_CH * 64; e += 256) {
            int o = e >> 6, cl = e & 63;
            swT[cl][o] = w_qkv[o * 256 + cc + cl];
        }
        for (int e = t; e < 64 * 64; e += 256) {
            int cl = e >> 6, ll = e & 63;
            sx[cl][ll] = xm[(cc + cl) * 64 + ll];
        }
        __syncthreads();
        const float4* swT4 = (const float4*)swT;     // 12 float4 per row
        #pragma unroll 4
        for (int cl = 0; cl < 64; ++cl) {
            float xv = sx[cl][l];
            float4 w0 = swT4[cl * 12 + og * 3 + 0];  // warp-uniform broadcast
            float4 w1 = swT4[cl * 12 + og * 3 + 1];
            float4 w2 = swT4[cl * 12 + og * 3 + 2];
            acc[0] += w0.x * xv; acc[1]  += w0.y * xv;
            acc[2] += w0.z * xv; acc[3]  += w0.w * xv;
            acc[4] += w1.x * xv; acc[5]  += w1.y * xv;
            acc[6] += w1.z * xv; acc[7]  += w1.w * xv;
            acc[8] += w2.x * xv; acc[9]  += w2.y * xv;
            acc[10]+= w2.z * xv; acc[11] += w2.w * xv;
        }
        __syncthreads();
    }

    const float* pos = axis ? pos_w : pos_h;
    #pragma unroll
    for (int j = 0; j < 12; ++j) {
        int o = og * 12 + j;
        float v = acc[j] * qs[o] + qsh[o];
        if (o < 32) v += pos[(o & 15) * 64 + l];   // pos added to q and k
        sT[l][o] = v;
    }
    __syncthreads();

    // ---- attention (threads 0..127: i = t&63, head = t>>6) ----
    if (t < 128) {
        int i  = t & 63;
        int qo = (t >> 6) * 8;

        float qreg[8];
        #pragma unroll
        for (int d = 0; d < 8; ++d) qreg[d] = sT[i][qo + d];

        float a[64];
        float m = -1e30f;
        #pragma unroll
        for (int j = 0; j < 64; ++j) {
            float s = 0.f;
            #pragma unroll
            for (int d = 0; d < 8; ++d) s += qreg[d] * sT[j][16 + qo + d];
            s *= 0.35355339059327373f;  // 8^-0.5
            a[j] = s;
            m = fmaxf(m, s);
        }
        float ssum = 0.f;
        #pragma unroll
        for (int j = 0; j < 64; ++j) {
            float e = __expf(a[j] - m);
            a[j] = e;
            ssum += e;
        }
        float inv = 1.f / ssum;

        float acc2[8] = {0.f, 0.f, 0.f, 0.f, 0.f, 0.f, 0.f, 0.f};
        #pragma unroll
        for (int j = 0; j < 64; ++j) {
            float aj = a[j];
            #pragma unroll
            for (int d = 0; d < 8; ++d) acc2[d] += aj * sT[j][32 + qo + d];
        }
        #pragma unroll
        for (int d = 0; d < 8; ++d) {
            float v = acc2[d] * inv;
            g_att[blk * NHKD * 64 + (qo + d) * 64 + i] = v;
            sM[qo + d][i] = v;
        }
    }
    __syncthreads();

    // ---- channel means (free here; kills k45's serial stage-1) ----
    {
        int ch = t >> 4, sub = t & 15;          // 16 ch x 16 threads
        float s = 0.f;
        #pragma unroll
        for (int k = 0; k < 4; ++k) s += sM[ch][sub + 16 * k];
        #pragma unroll
        for (int off = 8; off >= 1; off >>= 1)
            s += __shfl_xor_sync(0xffffffffu, s, off);
        if (sub == 0) g_mean[blk * NHKD + ch] = s * (1.f / 64.f);
    }
}

// ---------------------------------------------------------------------------
// K45: SE gate + P/Q. NOW 64 blocks (b,axis): gate chain duplicated per axis
// (latency-bound, duplication free), P/Q halved per thread.
// w_fusion prefetched to padded smem (conflict-free, latency overlapped).
// ---------------------------------------------------------------------------
__global__ void k45_gate_pq(const float* __restrict__ w_fusion,
                            const float* __restrict__ fs,
                            const float* __restrict__ fsh,
                            const float* __restrict__ wg1,
                            const float* __restrict__ g1s,
                            const float* __restrict__ g1sh,
                            const float* __restrict__ wg2,
                            const float* __restrict__ g2s,
                            const float* __restrict__ g2sh) {
    int blk  = blockIdx.x;        // b*2+axis
    int axis = blk & 1;
    int b    = blk >> 1;
    int t = threadIdx.x;
    int lane = t & 31, wrp = t >> 5;       // 8 warps

    __shared__ float swf[256][33];         // 33.8 KB padded w_fusion
    __shared__ float satt[NHKD * 64];      // 4 KB this axis' attention out
    __shared__ float meanf[32];
    __shared__ float y[256];
    __shared__ float t1[64];

    // prefetch (all independent; overlap DRAM latency)
    #pragma unroll
    for (int e = t; e < 256 * 32; e += 256)
        swf[e >> 5][e & 31] = w_fusion[e];
    {
        const float4* src = (const float4*)(g_att + blk * NHKD * 64);
        ((float4*)satt)[t] = src[t];       // 256 float4 = 1024 floats
    }
    if (t < 32) meanf[t] = g_mean[b * 32 + t];   // [h 16ch | w 16ch]
    __syncthreads();

    // stage 2: y = cbn(w_fusion @ meanf)  (smem weights, conflict-free)
    {
        float s = 0.f;
        #pragma unroll
        for (int c = 0; c < 32; ++c) s += swf[t][c] * meanf[c];
        y[t] = s * fs[t] + fsh[t];
    }
    __syncthreads();

    // stage 3: t1 = silu(cbn(wg1 @ y)) — warp-per-row, coalesced lanes
    #pragma unroll
    for (int o = wrp; o < 64; o += 8) {
        const float* r = wg1 + o * 256;
        float s = 0.f;
        #pragma unroll
        for (int i = 0; i < 8; ++i) {
            int c = lane + 32 * i;
            s += r[c] * y[c];
        }
        #pragma unroll
        for (int off = 16; off >= 1; off >>= 1)
            s += __shfl_xor_sync(0xffffffffu, s, off);
        if (lane == 0) {
            s = s * g1s[o] + g1sh[o];
            t1[o] = s / (1.f + __expf(-s));
        }
    }
    __syncthreads();

    // stage 4: gate = sigmoid(cbn(wg2 @ t1))
    float gate;
    {
        const float4* wr = (const float4*)(wg2 + t * 64);
        float s = 0.f;
        #pragma unroll
        for (int c4 = 0; c4 < 16; ++c4) {
            float4 wv = wr[c4];
            s += wv.x * t1[c4 * 4 + 0] + wv.y * t1[c4 * 4 + 1]
               + wv.z * t1[c4 * 4 + 2] + wv.w * t1[c4 * 4 + 3];
        }
        s = s * g2s[t] + g2sh[t];
        gate = 1.f / (1.f + __expf(-s));
    }

    // stage 5: this axis' P or Q row for o = t
    int o = t;
    float scale = fs[o] * gate * 0.1f;
    float bias  = axis ? 0.f : fsh[o] * gate * 0.1f;
    float w[16];
    #pragma unroll
    for (int c = 0; c < 16; ++c) w[c] = swf[o][axis * 16 + c];
    float* dst = (axis ? g_Q : g_P) + (b * 256 + o) * 64;
    const float4* base = (const float4*)satt;

    #pragma unroll
    for (int lg = 0; lg < 16; ++lg) {
        float4 acc = {0.f, 0.f, 0.f, 0.f};
        #pragma unroll
        for (int c = 0; c < 16; ++c) {
            float4 xv = base[c * 16 + lg];     // warp-uniform broadcast
            acc.x += w[c] * xv.x; acc.y += w[c] * xv.y;
            acc.z += w[c] * xv.z; acc.w += w[c] * xv.w;
        }
        float4 r;
        r.x = acc.x * scale + bias; r.y = acc.y * scale + bias;
        r.z = acc.z * scale + bias; r.w = acc.w * scale + bias;
        ((float4*)dst)[lg] = r;
    }
}

// ---------------------------------------------------------------------------
// K6: out[b,o,h,w] = x + P[b,o,h] + Q[b,o,w].  8192 blocks (b,o), 256 threads.
// (no cache hints — they measurably hurt in R6)
// ---------------------------------------------------------------------------
__global__ void k6_final(const float* __restrict__ x, float* __restrict__ out) {
    int blk = blockIdx.x;              // b*256+o
    __shared__ float  sp[64];
    __shared__ float4 sq4[16];
    int t = threadIdx.x;
    if (t < 64) sp[t] = g_P[blk * 64 + t];
    else if (t < 80) sq4[t - 64] = ((const float4*)(g_Q + blk * 64))[t - 64];
    __syncthreads();

    const float4* xi = (const float4*)(x + (size_t)blk * 4096);
    float4*       xo = (float4*)(out + (size_t)blk * 4096);
    #pragma unroll
    for (int i = 0; i < 4; ++i) {
        int j = t + 256 * i;
        float  p  = sp[j >> 4];
        float4 qv = sq4[j & 15];
        float4 xv = xi[j];
        float4 r;
        r.x = xv.x + p + qv.x;
        r.y = xv.y + p + qv.y;
        r.z = xv.z + p + qv.z;
        r.w = xv.w + p + qv.w;
        xo[j] = r;
    }
}

// ---------------------------------------------------------------------------
// Input identification by element count (robust to metadata ordering).
// ---------------------------------------------------------------------------
extern "C" void kernel_launch(void* const* d_in, const int* in_sizes, int n_in,
                              void* d_out, int out_size) {
    const float *x = 0, *w_qkv = 0, *qkv_scale = 0, *qkv_shift = 0;
    const float *pos_h = 0, *pos_w = 0, *w_fusion = 0;
    const float *fusion_scale = 0, *fusion_shift = 0;
    const float *w_g1 = 0, *g1_scale = 0, *g1_shift = 0;
    const float *w_g2 = 0, *g2_scale = 0, *g2_shift = 0;

    int n48 = 0, n64 = 0, n256 = 0, n1024 = 0, n16384 = 0;
    for (int i = 0; i < n_in; ++i) {
        const float* p = (const float*)d_in[i];
        switch (in_sizes[i]) {
            case 33554432: x = p; break;
            case 12288:    w_qkv = p; break;
            case 8192:     w_fusion = p; break;
            case 48:
                if (n48++ == 0) qkv_scale = p; else qkv_shift = p; break;
            case 1024:
                if (n1024++ == 0) pos_h = p; else pos_w = p; break;
            case 16384:
                if (n16384++ == 0) w_g1 = p; else w_g2 = p; break;
            case 64:
                if (n64++ == 0) g1_scale = p; else g1_shift = p; break;
            case 256:
                switch (n256++) {
                    case 0: fusion_scale = p; break;
                    case 1: fusion_shift = p; break;
                    case 2: g2_scale = p; break;
                    default: g2_shift = p; break;
                }
                break;
            default: break;
        }
    }
    float* out = (float*)d_out;

    k1_reduce<<<BB * CC, 256>>>(x);
    k23_qkv_attn<<<64, 256>>>(w_qkv, qkv_scale, qkv_shift, pos_h, pos_w);
    k45_gate_pq<<<64, 256>>>(w_fusion, fusion_scale, fusion_shift,
                             w_g1, g1_scale, g1_shift,
                             w_g2, g2_scale, g2_shift);
    k6_final<<<BB * CC, 256>>>(x, out);
}